// round 1
// baseline (speedup 1.0000x reference)
#include <cuda_runtime.h>

// LIF scan: B=16 batches, S=256 steps, H=128 hidden, N=64 neurons.
// Serial chain of T=S*H=32768 steps per (b,n). 1024 independent chains.
//
// Roles per block (one block per batch, 128 threads):
//   threads 0..63   : compute lanes, one neuron each. Serial scan, store
//                     pre-reset value v into SMEM tile (stride-65 rows,
//                     bank-conflict-free).
//   threads 64..127 : writer lanes. Drain previous tile to global with
//                     coalesced stores (recomputing spike/out from v),
//                     and prestage the next x-tile into SMEM.
// Double-buffered tiles, one __syncthreads per 64-step tile.

#define NB 16
#define NS 256
#define NH 128
#define NN 64
#define HT 64                      // time-steps per tile
#define NTILES (NS * (NH / HT))    // 512
#define RS (HT + 1)                // SMEM row stride (65) -> conflict-free
#define TOTE ((long long)NB * NS * NN * NH)   // 33554432 elements per half

__device__ __forceinline__ void drain_tile(
    int b, int pt, const float* __restrict__ src, const float* __restrict__ thr_s,
    float* __restrict__ outbuf, int rh)
{
    const int s    = pt >> 1;
    const int half = pt & 1;
    // out[b][s][rn][half*HT + rh]
    float* ob = outbuf + (((long long)b * NS + s) * NN) * NH + (long long)half * HT;
    float* sb = ob + TOTE;   // spikes half of the output buffer
    #pragma unroll 8
    for (int rn = 0; rn < NN; ++rn) {
        float v   = src[rn * RS + rh];     // lanes rh consecutive -> conflict-free
        float thn = thr_s[rn];             // broadcast LDS
        bool  sp  = v > thn;               // exact: v is the rounded fadd(acc,x)
        ob[rn * NH + rh] = sp ? v : 0.0f;
        sb[rn * NH + rh] = sp ? 1.0f : 0.0f;
    }
}

__global__ __launch_bounds__(128, 1)
void lif_kernel(const float* __restrict__ inputs,
                const float* __restrict__ threshes,
                const float* __restrict__ acc0,
                float* __restrict__ outbuf)
{
    __shared__ float buf[2][NN * RS];   // 2 x 64 x 65 floats = 33280 B
    __shared__ float xs[2][HT];         // staged input stream
    __shared__ float thr_s[NN];

    const int b   = blockIdx.x;
    const int tid = threadIdx.x;
    const float* xb = inputs + (long long)b * NS * NH;

    if (tid < NN) thr_s[tid] = threshes[tid];
    if (tid >= NN) {                    // stage x tile 0
        int lt = tid - NN;
        if (lt < HT) xs[0][lt] = xb[lt];
    }
    __syncthreads();

    // per-role persistent state
    const int   n   = tid;              // valid when tid < NN
    const float th  = (tid < NN) ? thr_s[tid] : 0.0f;
    float       acc = (tid < NN) ? acc0[b * NN + tid] : 0.0f;
    const int   lt  = tid - NN;         // valid when tid >= NN

    for (int tt = 0; tt < NTILES; ++tt) {
        if (tid < NN) {
            // -------- compute role: serial LIF chain over HT steps --------
            const float* __restrict__ xr = xs[tt & 1];
            float* __restrict__ row = &buf[tt & 1][n * RS];
            #pragma unroll 8
            for (int j = 0; j < HT; ++j) {
                float v = acc + xr[j];          // exact fadd order of reference
                acc = (v > th) ? 0.0f : v;      // FSETP(pred-as-data) + FSEL
                row[j] = v;                     // banks (n + j) % 32: conflict-free
            }
        } else {
            // -------- writer role: prestage next x, drain previous tile ---
            if (tt + 1 < NTILES && lt < HT)
                xs[(tt + 1) & 1][lt] = xb[(tt + 1) * HT + lt];
            if (tt > 0)
                drain_tile(b, tt - 1, buf[(tt - 1) & 1], thr_s, outbuf, lt);
        }
        __syncthreads();
    }

    // final tile drain
    if (tid >= NN)
        drain_tile(b, NTILES - 1, buf[(NTILES - 1) & 1], thr_s, outbuf, lt);
}

extern "C" void kernel_launch(void* const* d_in, const int* in_sizes, int n_in,
                              void* d_out, int out_size)
{
    const float* inputs   = (const float*)d_in[0];  // [B,S,H] = 524288
    const float* threshes = (const float*)d_in[1];  // [N] = 64
    const float* acc0     = (const float*)d_in[2];  // [B,N] = 1024
    float* out = (float*)d_out;                     // outs then spikes, 2*33554432 f32

    lif_kernel<<<NB, 128>>>(inputs, threshes, acc0, out);
}

// round 2
// speedup vs baseline: 1.6918x; 1.6918x over previous
#include <cuda_runtime.h>

// LIF scan, recurrence rewritten on the pre-reset value S:
//   S_{j+1} = (S_j > th) ? x_{j+1} : (S_j + x_{j+1})
// FADD and FSETP both read S_j (parallel), one FSEL closes the step:
// ~8-9 cycle chain instead of 12. Exact: on spike acc=0, 0+x==x bitwise.
// Seed: S_{-1}=acc0 (==0 in this problem) with th>=0 -> first compare false,
// so step 0 is exactly acc0 + x_0.
//
// Grid: 32 blocks = 16 batches x 2 neuron-groups of 32. 128 threads/block:
//   warp 0  : 32 compute chains (one neuron per lane), alone on its SMSP
//   warp 1  : stages the shared x-stream tile into SMEM
//   warps 2,3: drain previous tile to global, float4 stores, recomputing
//              out = sp?S:0 and spike = sp?1:0 from stored S.

#define NB 16
#define NS 256
#define NH 128
#define NN 64
#define NPB 32                    // neurons per block
#define HT 64                     // time-steps per tile
#define NTILES 512                // 32768 / HT
#define RS 65                     // SMEM row stride, conflict-free STS
#define TOTE ((long long)NB * NS * NN * NH)   // 33554432 per output half

__device__ __forceinline__ void drain_tile(
    int b, int g, int pt, const float* __restrict__ src,
    const float* __restrict__ thr_s, float* __restrict__ outbuf, int wl)
{
    const int s    = pt >> 1;
    const int half = pt & 1;
    float* ob = outbuf + (((long long)b * NS + s) * NN + g * NPB) * NH + half * HT;
    float* sb = ob + TOTE;
    // 512 quads per tile: idx -> n = idx>>4 (0..31), q = idx&15 (h-quad)
    #pragma unroll
    for (int it = 0; it < 8; ++it) {
        int idx = wl + it * 64;
        int n = idx >> 4, q = idx & 15;
        const float* r = src + n * RS + q * 4;
        float th = thr_s[n];
        float v0 = r[0], v1 = r[1], v2 = r[2], v3 = r[3];
        float4 o, sp;
        bool p0 = v0 > th, p1 = v1 > th, p2 = v2 > th, p3 = v3 > th;
        o.x = p0 ? v0 : 0.0f;  sp.x = p0 ? 1.0f : 0.0f;
        o.y = p1 ? v1 : 0.0f;  sp.y = p1 ? 1.0f : 0.0f;
        o.z = p2 ? v2 : 0.0f;  sp.z = p2 ? 1.0f : 0.0f;
        o.w = p3 ? v3 : 0.0f;  sp.w = p3 ? 1.0f : 0.0f;
        *(float4*)(ob + n * NH + q * 4) = o;
        *(float4*)(sb + n * NH + q * 4) = sp;
    }
}

#define STEP(XV, J)                                   \
    do {                                              \
        float u_ = S + (XV);                          \
        bool  p_ = S > th;                            \
        S = p_ ? (XV) : u_;                           \
        row[(J)] = S;                                 \
    } while (0)

__global__ __launch_bounds__(128, 1)
void lif_kernel(const float* __restrict__ inputs,
                const float* __restrict__ threshes,
                const float* __restrict__ acc0,
                float* __restrict__ outbuf)
{
    __shared__ float buf[2][NPB * RS];   // 2 x 32 x 65 floats = 16.6 KB
    __shared__ float xs[2][HT];
    __shared__ float thr_s[NPB];

    const int b    = blockIdx.x >> 1;
    const int g    = blockIdx.x & 1;
    const int tid  = threadIdx.x;
    const int wid  = tid >> 5;
    const int lane = tid & 31;
    const float* xb = inputs + (long long)b * NS * NH;

    if (tid < NPB) thr_s[tid] = threshes[g * NPB + tid];
    if (wid == 1) {                       // stage x tile 0
        xs[0][lane]      = xb[lane];
        xs[0][lane + 32] = xb[lane + 32];
    }
    __syncthreads();

    if (wid == 0) {
        // ---------------- compute warp: 32 serial chains ----------------
        const int   n  = lane;
        const float th = thr_s[n];
        float S = acc0[b * NN + g * NPB + n];   // virtual S_{-1}; exact (see top)
        for (int tt = 0; tt < NTILES; ++tt) {
            const float* __restrict__ xr  = xs[tt & 1];
            float* __restrict__       row = &buf[tt & 1][n * RS];
            #pragma unroll
            for (int j = 0; j < HT; j += 8) {
                // prefetch x off the chain
                float x0 = xr[j+0], x1 = xr[j+1], x2 = xr[j+2], x3 = xr[j+3];
                float x4 = xr[j+4], x5 = xr[j+5], x6 = xr[j+6], x7 = xr[j+7];
                STEP(x0, j+0); STEP(x1, j+1); STEP(x2, j+2); STEP(x3, j+3);
                STEP(x4, j+4); STEP(x5, j+5); STEP(x6, j+6); STEP(x7, j+7);
            }
            __syncthreads();
        }
    } else if (wid == 1) {
        // ---------------- x-stager ----------------
        for (int tt = 0; tt < NTILES; ++tt) {
            if (tt + 1 < NTILES) {
                xs[(tt + 1) & 1][lane]      = xb[(tt + 1) * HT + lane];
                xs[(tt + 1) & 1][lane + 32] = xb[(tt + 1) * HT + lane + 32];
            }
            __syncthreads();
        }
    } else {
        // ---------------- writers (warps 2,3) ----------------
        const int wl = tid - 64;   // 0..63
        for (int tt = 0; tt < NTILES; ++tt) {
            if (tt > 0)
                drain_tile(b, g, tt - 1, buf[(tt - 1) & 1], thr_s, outbuf, wl);
            __syncthreads();
        }
        drain_tile(b, g, NTILES - 1, buf[(NTILES - 1) & 1], thr_s, outbuf, wl);
    }
}

extern "C" void kernel_launch(void* const* d_in, const int* in_sizes, int n_in,
                              void* d_out, int out_size)
{
    const float* inputs   = (const float*)d_in[0];  // [B,S,H]
    const float* threshes = (const float*)d_in[1];  // [N]
    const float* acc0     = (const float*)d_in[2];  // [B,N]
    float* out = (float*)d_out;                     // outs then spikes (f32)

    lif_kernel<<<NB * 2, 128>>>(inputs, threshes, acc0, out);
}

// round 3
// speedup vs baseline: 1.7410x; 1.0291x over previous
#include <cuda_runtime.h>

// LIF scan on pre-reset value S:  S_{j+1} = (S_j > th) ? x_{j+1} : S_j + x_{j+1}
// Forced SASS data path: setp.gt.f32 + selp.f32  ->  FSETP(4) -> FSEL(4),
// FADD off-path. ~8-cycle recurrence instead of predicated-mov ~17.
// Exact: on spike acc=0 and 0+x==x; seed S_{-1}=acc0 (both branches equal
// when acc0==0).
//
// Grid: 32 blocks = 16 batches x 2 neuron-groups of 32. 96 threads:
//   warp 0    : 32 serial chains (one neuron/lane), alone on SMSP0
//   warps 1,2 : stage next x tile + drain previous S tile to global
//               (recompute out/spike from S), LDS.128 / STG.128.
// Tile = 128 steps = one full s index; 256 tiles, 1 __syncthreads per tile.

#define NB 16
#define NS 256
#define NH 128
#define NN 64
#define NPB 32
#define HT 128                     // steps per tile == NH
#define NTILES 256
#define RS 132                     // row stride (floats); 16B-aligned rows,
                                   // 16B-chunk idx = 33n+q -> conflict-free
#define TOTE ((long long)NB * NS * NN * NH)

#define STEP(XV, DST) do {                                             \
    float u_, Sn_;                                                     \
    asm("add.f32 %0, %1, %2;" : "=f"(u_) : "f"(S), "f"(XV));           \
    asm("{ .reg .pred p_; setp.gt.f32 p_, %2, %3;"                     \
        "  selp.f32 %0, %4, %1, p_; }"                                 \
        : "=f"(Sn_) : "f"(u_), "f"(S), "f"(th), "f"(XV));              \
    S = Sn_; (DST) = S;                                                \
} while (0)

__device__ __forceinline__ void drain_tile(
    int b, int g, int s, const float* __restrict__ src,
    const float* __restrict__ thr_s, float* __restrict__ outbuf, int wl)
{
    float* ob = outbuf + (((long long)b * NS + s) * NN + g * NPB) * NH;
    float* sb = ob + TOTE;
    // 1024 quads: idx = wl + it*64 ; n = idx>>5 (0..31), q = idx&31 (h-quad)
    #pragma unroll
    for (int it = 0; it < 16; ++it) {
        int idx = wl + it * 64;
        int n = idx >> 5, q = idx & 31;
        float4 v = *(const float4*)(src + n * RS + q * 4);   // LDS.128
        float th = thr_s[n];
        bool p0 = v.x > th, p1 = v.y > th, p2 = v.z > th, p3 = v.w > th;
        float4 o, sp;
        o.x = p0 ? v.x : 0.0f;  sp.x = p0 ? 1.0f : 0.0f;
        o.y = p1 ? v.y : 0.0f;  sp.y = p1 ? 1.0f : 0.0f;
        o.z = p2 ? v.z : 0.0f;  sp.z = p2 ? 1.0f : 0.0f;
        o.w = p3 ? v.w : 0.0f;  sp.w = p3 ? 1.0f : 0.0f;
        *(float4*)(ob + n * NH + q * 4) = o;                 // STG.128
        *(float4*)(sb + n * NH + q * 4) = sp;
    }
}

__global__ __launch_bounds__(96, 1)
void lif_kernel(const float* __restrict__ inputs,
                const float* __restrict__ threshes,
                const float* __restrict__ acc0,
                float* __restrict__ outbuf)
{
    __shared__ float buf[2][NPB * RS];   // 2 x 32 x 132 x 4B = 33.8 KB
    __shared__ float xs[2][HT];
    __shared__ float thr_s[NPB];

    const int b    = blockIdx.x >> 1;
    const int g    = blockIdx.x & 1;
    const int tid  = threadIdx.x;
    const int wid  = tid >> 5;
    const int lane = tid & 31;
    const float* xb = inputs + (long long)b * NS * NH;

    if (tid < NPB) thr_s[tid] = threshes[g * NPB + tid];
    if (wid == 1) {                        // stage x tile 0 (128 floats)
        *(float4*)(&xs[0][lane * 4]) = *(const float4*)(xb + lane * 4);
    }
    __syncthreads();

    if (wid == 0) {
        // ------------- compute warp: 32 serial chains -------------
        const float th = thr_s[lane];
        float S = acc0[b * NN + g * NPB + lane];
        for (int tt = 0; tt < NTILES; ++tt) {
            const float* __restrict__ xr  = xs[tt & 1];
            float* __restrict__       row = &buf[tt & 1][lane * RS];
            #pragma unroll
            for (int j = 0; j < HT; j += 8) {
                float x0 = xr[j+0], x1 = xr[j+1], x2 = xr[j+2], x3 = xr[j+3];
                float x4 = xr[j+4], x5 = xr[j+5], x6 = xr[j+6], x7 = xr[j+7];
                float4 a, c;
                STEP(x0, a.x); STEP(x1, a.y); STEP(x2, a.z); STEP(x3, a.w);
                STEP(x4, c.x); STEP(x5, c.y); STEP(x6, c.z); STEP(x7, c.w);
                *(float4*)(row + j)     = a;     // STS.128, conflict-free
                *(float4*)(row + j + 4) = c;
            }
            __syncthreads();
        }
    } else {
        // ------------- writers: stage x, drain S tiles -------------
        const int wl = tid - 32;             // 0..63
        for (int tt = 0; tt < NTILES; ++tt) {
            if (tt + 1 < NTILES && wl < 32)  // stage next x tile (warp 1)
                *(float4*)(&xs[(tt + 1) & 1][wl * 4]) =
                    *(const float4*)(xb + (tt + 1) * HT + wl * 4);
            if (tt > 0)
                drain_tile(b, g, tt - 1, buf[(tt - 1) & 1], thr_s, outbuf, wl);
            __syncthreads();
        }
        drain_tile(b, g, NTILES - 1, buf[(NTILES - 1) & 1], thr_s, outbuf, wl);
    }
}

extern "C" void kernel_launch(void* const* d_in, const int* in_sizes, int n_in,
                              void* d_out, int out_size)
{
    const float* inputs   = (const float*)d_in[0];  // [B,S,H]
    const float* threshes = (const float*)d_in[1];  // [N]
    const float* acc0     = (const float*)d_in[2];  // [B,N]
    float* out = (float*)d_out;                     // outs then spikes (f32)

    lif_kernel<<<NB * 2, 96>>>(inputs, threshes, acc0, out);
}

// round 4
// speedup vs baseline: 2.4697x; 1.4185x over previous
#include <cuda_runtime.h>

// LIF scan, predicate-free recurrence:
//   f  = (S <= th) ? 1.0f : 0.0f        (FSET, fixed-lat 4, no predicate)
//   S' = fmaf(S, f, x)                  (FFMA, fixed-lat 4)
// Chain = 8 cycles/step. Bit-exact: keep-path fma(S,1,x) == fadd(S,x);
// spike-path fma(S,0,x) == x (S>th>0 so S*0=+0).
//
// Grid: 32 blocks = 16 batches x 2 neuron-groups of 32. 96 threads:
//   warp 0    : 32 serial chains (one neuron/lane)
//   warps 1,2 : stage next x tile + drain previous S tile to global
//               (recompute out/spike from stored pre-reset S), LDS/STG.128.
// Tile = 128 steps; 256 tiles; 1 __syncthreads per tile.

#define NB 16
#define NS 256
#define NH 128
#define NN 64
#define NPB 32
#define HT 128
#define NTILES 256
#define RS 132                     // floats; 16B chunk idx = 33n+q -> conflict-free
#define TOTE ((long long)NB * NS * NN * NH)

#define STEP(XV, DST) do {                                                 \
    float f_;                                                              \
    asm("set.le.f32.f32 %0, %1, %2;" : "=f"(f_) : "f"(S), "f"(th));        \
    asm("fma.rn.f32 %0, %1, %2, %3;" : "=f"(S) : "f"(S), "f"(f_), "f"(XV));\
    (DST) = S;                                                             \
} while (0)

__device__ __forceinline__ void drain_tile(
    int b, int g, int s, const float* __restrict__ src,
    const float* __restrict__ thr_s, float* __restrict__ outbuf, int wl)
{
    float* ob = outbuf + (((long long)b * NS + s) * NN + g * NPB) * NH;
    float* sb = ob + TOTE;
    #pragma unroll
    for (int it = 0; it < 16; ++it) {
        int idx = wl + it * 64;
        int n = idx >> 5, q = idx & 31;
        float4 v = *(const float4*)(src + n * RS + q * 4);   // LDS.128
        float th = thr_s[n];
        bool p0 = v.x > th, p1 = v.y > th, p2 = v.z > th, p3 = v.w > th;
        float4 o, sp;
        o.x = p0 ? v.x : 0.0f;  sp.x = p0 ? 1.0f : 0.0f;
        o.y = p1 ? v.y : 0.0f;  sp.y = p1 ? 1.0f : 0.0f;
        o.z = p2 ? v.z : 0.0f;  sp.z = p2 ? 1.0f : 0.0f;
        o.w = p3 ? v.w : 0.0f;  sp.w = p3 ? 1.0f : 0.0f;
        *(float4*)(ob + n * NH + q * 4) = o;                 // STG.128
        *(float4*)(sb + n * NH + q * 4) = sp;
    }
}

__global__ __launch_bounds__(96, 1)
void lif_kernel(const float* __restrict__ inputs,
                const float* __restrict__ threshes,
                const float* __restrict__ acc0,
                float* __restrict__ outbuf)
{
    __shared__ float buf[2][NPB * RS];   // 33.8 KB
    __shared__ float xs[2][HT];
    __shared__ float thr_s[NPB];

    const int b    = blockIdx.x >> 1;
    const int g    = blockIdx.x & 1;
    const int tid  = threadIdx.x;
    const int wid  = tid >> 5;
    const int lane = tid & 31;
    const float* xb = inputs + (long long)b * NS * NH;

    if (tid < NPB) thr_s[tid] = threshes[g * NPB + tid];
    if (wid == 1)                          // stage x tile 0 (128 floats)
        *(float4*)(&xs[0][lane * 4]) = *(const float4*)(xb + lane * 4);
    __syncthreads();

    if (wid == 0) {
        // ------------- compute warp: 32 serial chains -------------
        const float th = thr_s[lane];
        float S = acc0[b * NN + g * NPB + lane];
        for (int tt = 0; tt < NTILES; ++tt) {
            const float* __restrict__ xr  = xs[tt & 1];
            float* __restrict__       row = &buf[tt & 1][lane * RS];
            #pragma unroll
            for (int j = 0; j < HT; j += 8) {
                float4 xa = *(const float4*)(xr + j);        // LDS.128
                float4 xc = *(const float4*)(xr + j + 4);    // LDS.128
                float4 a, c;
                STEP(xa.x, a.x); STEP(xa.y, a.y); STEP(xa.z, a.z); STEP(xa.w, a.w);
                STEP(xc.x, c.x); STEP(xc.y, c.y); STEP(xc.z, c.z); STEP(xc.w, c.w);
                *(float4*)(row + j)     = a;                 // STS.128
                *(float4*)(row + j + 4) = c;
            }
            __syncthreads();
        }
    } else {
        // ------------- writers: stage x, drain S tiles -------------
        const int wl = tid - 32;             // 0..63
        for (int tt = 0; tt < NTILES; ++tt) {
            if (tt + 1 < NTILES && wl < 32)
                *(float4*)(&xs[(tt + 1) & 1][wl * 4]) =
                    *(const float4*)(xb + (tt + 1) * HT + wl * 4);
            if (tt > 0)
                drain_tile(b, g, tt - 1, buf[(tt - 1) & 1], thr_s, outbuf, wl);
            __syncthreads();
        }
        drain_tile(b, g, NTILES - 1, buf[(NTILES - 1) & 1], thr_s, outbuf, wl);
    }
}

extern "C" void kernel_launch(void* const* d_in, const int* in_sizes, int n_in,
                              void* d_out, int out_size)
{
    const float* inputs   = (const float*)d_in[0];  // [B,S,H]
    const float* threshes = (const float*)d_in[1];  // [N]
    const float* acc0     = (const float*)d_in[2];  // [B,N]
    float* out = (float*)d_out;                     // outs then spikes (f32)

    lif_kernel<<<NB * 2, 96>>>(inputs, threshes, acc0, out);
}